// round 15
// baseline (speedup 1.0000x reference)
#include <cuda_runtime.h>
#include <cuda_fp16.h>
#include <math.h>
#include <stdint.h>

#define Bsz 2
#define SEQ 2048
#define HID 2048
#define NH 8
#define HD 256
#define MROWS (Bsz*SEQ)          // 4096
#define SCALE 0.0625f
#define LO_SCALE 1024.0f
#define INV_LO (1.0f/1024.0f)

// ---------------- scratch (packed hi/lo fp16, v1 format) ----------------
// packed row format: per 32-element k block: 64B hi fp16, then 64B lo fp16 (lo scaled x1024).
__device__ __align__(128) char g_hidp[(size_t)MROWS * HID * 4];
__device__ __align__(128) char g_wqp [(size_t)HID * HID * 4];
__device__ __align__(128) char g_wkp [(size_t)HD * HID * 4];
__device__ __align__(128) char g_wvp [(size_t)HD * HID * 4];
__device__ __align__(128) char g_wop [(size_t)HID * HID * 4];
__device__ __align__(128) char g_qp  [(size_t)MROWS * NH * HD * 4];
__device__ __align__(128) char g_kp  [(size_t)MROWS * HD * 4];
__device__ __align__(128) char g_vtp [(size_t)Bsz * HD * SEQ * 4];
__device__ __align__(128) char g_attnp[(size_t)MROWS * NH * HD * 4];
__device__ __align__(128) float g_scores[(size_t)Bsz * NH * SEQ * SEQ];
__device__ float g_cos[SEQ * 128];
__device__ float g_sin[SEQ * 128];

// ---------------- helpers ----------------
#define SWZ(x) ((x) ^ (((x) >> 3) & 0x70))

__device__ __forceinline__ uint32_t smem_u32(const void* p) {
    uint32_t a;
    asm("{ .reg .u64 t; cvta.to.shared.u64 t, %1; cvt.u32.u64 %0, t; }"
        : "=r"(a) : "l"(p));
    return a;
}

#define CP16(dst, src) \
    asm volatile("cp.async.ca.shared.global [%0], [%1], 16;" \
                 :: "r"(dst), "l"(src) : "memory")
#define CP_COMMIT() asm volatile("cp.async.commit_group;" ::: "memory")
#define CP_WAIT2()  asm volatile("cp.async.wait_group 2;" ::: "memory")
#define CP_WAIT1()  asm volatile("cp.async.wait_group 1;" ::: "memory")
#define CP_WAIT0()  asm volatile("cp.async.wait_group 0;" ::: "memory")

#define LDM4(r, a)                                                            \
    asm volatile("ldmatrix.sync.aligned.m8n8.x4.shared.b16 {%0,%1,%2,%3}, [%4];" \
        : "=r"((r)[0]), "=r"((r)[1]), "=r"((r)[2]), "=r"((r)[3]) : "r"(a))

#define MMA_F32(d, a, b0, b1)                                                 \
    asm volatile("mma.sync.aligned.m16n8k16.row.col.f32.f16.f16.f32 "         \
        "{%0,%1,%2,%3},{%4,%5,%6,%7},{%8,%9},{%0,%1,%2,%3};"                  \
        : "+f"((d)[0]), "+f"((d)[1]), "+f"((d)[2]), "+f"((d)[3])              \
        : "r"((a)[0]), "r"((a)[1]), "r"((a)[2]), "r"((a)[3]),                 \
          "r"(b0), "r"(b1))

#define MMA_F16(d, a, b0, b1)                                                 \
    asm volatile("mma.sync.aligned.m16n8k16.row.col.f16.f16.f16.f16 "         \
        "{%0,%1},{%2,%3,%4,%5},{%6,%7},{%0,%1};"                              \
        : "+r"((d)[0]), "+r"((d)[1])                                          \
        : "r"((a)[0]), "r"((a)[1]), "r"((a)[2]), "r"((a)[3]),                 \
          "r"(b0), "r"(b1))

__device__ __forceinline__ void split_hl(float v, __half& h, __half& l) {
    h = __float2half_rn(v);
    l = __float2half_rn((v - __half2float(h)) * LO_SCALE);
}

// ---------------- pre-convert fp32 -> packed ----------------
__global__ __launch_bounds__(256)
void cvt_pack_kernel(const float* __restrict__ src, char* __restrict__ dst,
                     long n_e4, int K)
{
    long stride = (long)gridDim.x * blockDim.x;
    for (long e4 = (long)blockIdx.x * blockDim.x + threadIdx.x; e4 < n_e4; e4 += stride) {
        long e = e4 * 4;
        long row = e / K;
        int kk = (int)(e % K);
        float4 v = *(const float4*)(src + e);
        __half h0, h1, h2, h3, l0, l1, l2, l3;
        split_hl(v.x, h0, l0); split_hl(v.y, h1, l1);
        split_hl(v.z, h2, l2); split_hl(v.w, h3, l3);
        __half2 hA = __halves2half2(h0, h1);
        __half2 hB = __halves2half2(h2, h3);
        __half2 lA = __halves2half2(l0, l1);
        __half2 lB = __halves2half2(l2, l3);
        char* out = dst + row * ((long)K * 4) + (kk >> 5) * 128 + (kk & 31) * 2;
        *(uint2*)out        = make_uint2(*(uint32_t*)&hA, *(uint32_t*)&hB);
        *(uint2*)(out + 64) = make_uint2(*(uint32_t*)&lA, *(uint32_t*)&lB);
    }
}

// ---------------- HMMA GEMM on packed operands ----------------
// C[m,n] = alpha * sum_k A[m,k]*B[n,k]; A,B packed v1 (pitch bytes pa/pb).
// A consumed hi-only; B hi+lo. CTA 128m x 64n, 8 warps (4m x 2n), warp 32x32,
// BK=32 per iter, 4 stages x 16KB, 3 CTAs/SM.
// Stage 16KB: A-hi 8KB (two global rows per 128B line) + B hi+lo 8KB.
#define STG(s) ((s) * 16384)
#define SM_TOTAL 65536

__global__ __launch_bounds__(256, 3)
void tc_gemm(const char* __restrict__ A, const char* __restrict__ B,
             char* __restrict__ C, int K,
             long pa, long pb, long pc,
             int zdiv, long za_div, long za_mod, long zb_div, long zb_mod,
             long zc_div, long zc_mod, float alpha,
             int causal, int kcausal, int pack_out)
{
    extern __shared__ char smem[];
    int z = blockIdx.z;
    A += (long)(z / zdiv) * za_div + (long)(z % zdiv) * za_mod;
    B += (long)(z / zdiv) * zb_div + (long)(z % zdiv) * zb_mod;
    C += (long)(z / zdiv) * zc_div + (long)(z % zdiv) * zc_mod;
    int bm = blockIdx.y * 128;
    int bn = blockIdx.x * 64;
    if (causal && bn > bm + 127) return;
    if (kcausal && K > bm + 128) K = bm + 128;

    uint32_t sb = smem_u32(smem);
    int tid = threadIdx.x, lane = tid & 31, wid = tid >> 5;
    int wm = wid >> 1;          // 0..3 (32-row slab)
    int wn = wid & 1;           // 0..1 (32-col slab)

// iter i2 covers k = i2*32 .. i2*32+31 (one packed 32-block)
// A-hi smem layout: global row r at (r&63)*128 + (r>>6)*64, 4x16B chunks.
#define ISSUE_STAGE(st, i2) do {                                              \
    _Pragma("unroll")                                                         \
    for (int j = 0; j < 2; j++) {  /* A hi-only: 512 x 16B */                 \
        int idx = tid + j * 256;                                              \
        int r = idx >> 2, c = idx & 3;                                        \
        uint32_t sw = SWZ((r & 63) * 128 + (r >> 6) * 64 + c * 16);           \
        CP16(sb + STG(st) + sw,                                               \
             A + (long)(bm + r) * pa + (long)(i2) * 128 + c * 16);            \
    }                                                                         \
    _Pragma("unroll")                                                         \
    for (int j = 0; j < 2; j++) {  /* B hi+lo: 64 rows x 8 chunks */          \
        int idx = tid + j * 256;                                              \
        int r = idx >> 3, c = idx & 7;                                        \
        uint32_t sw = SWZ(r * 128 + c * 16);                                  \
        CP16(sb + STG(st) + 8192 + sw,                                        \
             B + (long)(bn + r) * pb + (long)(i2) * 128 + c * 16);            \
    }                                                                         \
    CP_COMMIT();                                                              \
} while (0)

    float acc[2][4][4] = {};
    uint32_t acc16[2][4][2] = {};
    const int niter = K / 32;

    ISSUE_STAGE(0, 0);
    if (niter > 1) ISSUE_STAGE(1, 1);
    if (niter > 2) ISSUE_STAGE(2, 2);

    const int b_off0 = (wn * 32 + (lane & 7) + ((lane >> 4) & 1) * 8) * 128
                     + ((lane >> 3) & 1) * 16;

    for (int i = 0; i < niter; i++) {
        int remaining = niter - 1 - i;
        if (remaining >= 2)      CP_WAIT2();
        else if (remaining == 1) CP_WAIT1();
        else                     CP_WAIT0();
        __syncthreads();   // stage i%4 ready; all warps done MMA(i-1)

        int nst = i + 3;
        if (nst < niter) ISSUE_STAGE(nst & 3, nst);

        uint32_t aB = sb + STG(i & 3);
        uint32_t bB = aB + 8192;
        #pragma unroll
        for (int ks = 0; ks < 2; ks++) {     // 2 x k16 chunks within 32 k's
            uint32_t ah[2][4];
            #pragma unroll
            for (int mt = 0; mt < 2; mt++) {
                int r = wm * 32 + mt * 16 + (lane & 15);
                int off = (r & 63) * 128 + (r >> 6) * 64 + ks * 32 + (lane >> 4) * 16;
                LDM4(ah[mt], aB + SWZ(off));
            }
            #pragma unroll
            for (int np = 0; np < 2; np++) {
                uint32_t bh[4], bl[4];
                int off = b_off0 + np * 16 * 128 + ks * 32;
                LDM4(bh, bB + SWZ(off));
                LDM4(bl, bB + SWZ(off + 64));
                #pragma unroll
                for (int mt = 0; mt < 2; mt++) {
                    #pragma unroll
                    for (int t = 0; t < 2; t++) {
                        float*    d = acc[mt][np * 2 + t];
                        uint32_t* c = acc16[mt][np * 2 + t];
                        MMA_F32(d, ah[mt], bh[t * 2], bh[t * 2 + 1]);
                        MMA_F16(c, ah[mt], bl[t * 2], bl[t * 2 + 1]);
                    }
                }
            }
        }
    }

    // epilogue: merge f32 main + f16 correction (x1024)
    // pack_out: 0 = fp32 linear, 1 = packed hi+lo, 2 = packed hi-only
    int r0 = bm + wm * 32 + (lane >> 2);
    int c0 = bn + wn * 32 + (lane & 3) * 2;
    #pragma unroll
    for (int mt = 0; mt < 2; mt++) {
        #pragma unroll
        for (int nt = 0; nt < 4; nt++) {
            float* d = acc[mt][nt];
            uint32_t* cc = acc16[mt][nt];
            int c = c0 + nt * 8;
            #pragma unroll
            for (int half = 0; half < 2; half++) {
                long row = r0 + mt * 16 + half * 8;
                __half2 cr = *(__half2*)&cc[half];
                float v0 = (d[half * 2 + 0] + __low2float(cr)  * INV_LO) * alpha;
                float v1 = (d[half * 2 + 1] + __high2float(cr) * INV_LO) * alpha;
                if (pack_out) {
                    __half h0, h1, l0, l1;
                    split_hl(v0, h0, l0); split_hl(v1, h1, l1);
                    __half2 hp = __halves2half2(h0, h1);
                    char* base = C + row * pc + (c >> 5) * 128 + (c & 31) * 2;
                    *(uint32_t*)base = *(uint32_t*)&hp;
                    if (pack_out == 1) {
                        __half2 lp = __halves2half2(l0, l1);
                        *(uint32_t*)(base + 64) = *(uint32_t*)&lp;
                    }
                } else {
                    *(float2*)(C + row * pc + (long)c * 4) = make_float2(v0, v1);
                }
            }
        }
    }
}

// ---------------- RoPE ----------------
__global__ void rope_table_kernel()
{
    int d = blockIdx.x;
    double inv = exp(-((double)d / 128.0) * 9.210340371976184);
    const double INV2PI = 0.15915494309189535;
    const double PI2_HI = 6.283185307179586;
    const double PI2_LO = 2.4492935982947064e-16;
    for (int s = threadIdx.x; s < SEQ; s += blockDim.x) {
        double ang = (double)s * inv;
        double n = rint(ang * INV2PI);
        double r = fma(-n, PI2_HI, ang);
        r = fma(-n, PI2_LO, r);
        float rf = (float)r;
        g_cos[s * 128 + d] = cosf(rf);
        g_sin[s * 128 + d] = sinf(rf);
    }
}

__global__ void rope_apply_kernel(char* __restrict__ x, int heads, long pitch)
{
    long blk = blockIdx.x;
    long rowIdx = blk / heads;
    int h = (int)(blk % heads);
    int s = (int)(rowIdx % SEQ);
    int d = threadIdx.x;
    char* base = x + rowIdx * pitch + (long)h * 1024;

    int off1 = (d >> 5) * 128 + (d & 31) * 2;
    int e2 = d + 128;
    int off2 = (e2 >> 5) * 128 + (e2 & 31) * 2;

    float x1 = __half2float(*(__half*)(base + off1))
             + __half2float(*(__half*)(base + off1 + 64)) * INV_LO;
    float x2 = __half2float(*(__half*)(base + off2))
             + __half2float(*(__half*)(base + off2 + 64)) * INV_LO;
    float c  = g_cos[s * 128 + d];
    float si = g_sin[s * 128 + d];
    float y1 = x1 * c - x2 * si;
    float y2 = x2 * c + x1 * si;

    __half h1, l1, h2, l2;
    split_hl(y1, h1, l1); split_hl(y2, h2, l2);
    *(__half*)(base + off1)      = h1;
    *(__half*)(base + off1 + 64) = l1;
    *(__half*)(base + off2)      = h2;
    *(__half*)(base + off2 + 64) = l2;
}

// ---------------- causal softmax: fp32 in, packed fp16 hi out ------------
__global__ __launch_bounds__(256)
void softmax_kernel(float* __restrict__ scores)
{
    long row = blockIdx.x;
    int s = (int)(row % SEQ);
    int valid = s + 1;
    float* p = scores + row * (long)SEQ;
    int tid = threadIdx.x;

    float vals[8];
    float mx = -INFINITY;
    #pragma unroll
    for (int i = 0; i < 8; i++) {
        int c = tid + i * 256;
        vals[i] = (c < valid) ? p[c] : -INFINITY;
        mx = fmaxf(mx, vals[i]);
    }
    __shared__ float red[8];
    #pragma unroll
    for (int o = 16; o > 0; o >>= 1) mx = fmaxf(mx, __shfl_xor_sync(0xffffffffu, mx, o));
    if ((tid & 31) == 0) red[tid >> 5] = mx;
    __syncthreads();
    if (tid < 32) {
        float m = (tid < 8) ? red[tid] : -INFINITY;
        #pragma unroll
        for (int o = 4; o > 0; o >>= 1) m = fmaxf(m, __shfl_xor_sync(0xffffffffu, m, o));
        if (tid == 0) red[0] = m;
    }
    __syncthreads();
    mx = red[0];

    float sum = 0.f;
    #pragma unroll
    for (int i = 0; i < 8; i++) {
        int c = tid + i * 256;
        float e = (c < valid) ? __expf(vals[i] - mx) : 0.f;
        vals[i] = e;
        sum += e;
    }
    __shared__ float red2[8];
    #pragma unroll
    for (int o = 16; o > 0; o >>= 1) sum += __shfl_xor_sync(0xffffffffu, sum, o);
    if ((tid & 31) == 0) red2[tid >> 5] = sum;
    __syncthreads();
    if (tid < 32) {
        float m = (tid < 8) ? red2[tid] : 0.f;
        #pragma unroll
        for (int o = 4; o > 0; o >>= 1) m += __shfl_xor_sync(0xffffffffu, m, o);
        if (tid == 0) red2[0] = m;
    }
    __syncthreads();
    float inv = 1.0f / red2[0];

    char* pc = (char*)p;
    #pragma unroll
    for (int i = 0; i < 8; i++) {
        int c = tid + i * 256;
        float e = vals[i] * inv;
        char* base = pc + (c >> 5) * 128 + (c & 31) * 2;
        *(__half*)base = __float2half_rn(e);
    }
}

// ---------------- launch ----------------
extern "C" void kernel_launch(void* const* d_in, const int* in_sizes, int n_in,
                              void* d_out, int out_size)
{
    const float* hidden = (const float*)d_in[0];
    const float* Wq = (const float*)d_in[3];
    const float* Wk = (const float*)d_in[4];
    const float* Wv = (const float*)d_in[5];
    const float* Wo = (const float*)d_in[6];
    char* out = (char*)d_out;

    char *hidp, *wqp, *wkp, *wvp, *wop, *qp, *kp, *vtp, *attnp;
    float* sc;
    cudaGetSymbolAddress((void**)&hidp,  g_hidp);
    cudaGetSymbolAddress((void**)&wqp,   g_wqp);
    cudaGetSymbolAddress((void**)&wkp,   g_wkp);
    cudaGetSymbolAddress((void**)&wvp,   g_wvp);
    cudaGetSymbolAddress((void**)&wop,   g_wop);
    cudaGetSymbolAddress((void**)&qp,    g_qp);
    cudaGetSymbolAddress((void**)&kp,    g_kp);
    cudaGetSymbolAddress((void**)&vtp,   g_vtp);
    cudaGetSymbolAddress((void**)&attnp, g_attnp);
    cudaGetSymbolAddress((void**)&sc,    g_scores);

    cudaFuncSetAttribute(tc_gemm, cudaFuncAttributeMaxDynamicSharedMemorySize, SM_TOTAL);

    const long P_HID = (long)HID * 4;   // 8192B pitch
    const long P_HD  = (long)HD * 4;    // 1024B pitch
    const long P_SEQ = (long)SEQ * 4;   // 8192B pitch

    // launches ordered so Q GEMM is index 3 (ncu profiles launch idx 3)
    cvt_pack_kernel<<<2048, 256>>>(hidden, hidp, (long)MROWS * HID / 4, HID);  // 0
    cvt_pack_kernel<<<1024, 256>>>(Wq, wqp, (long)HID * HID / 4, HID);         // 1
    cvt_pack_kernel<<<256,  256>>>(Wk, wkp, (long)HD * HID / 4, HID);          // 2

    // 3: Q = hidden @ Wq^T -> packed q [4096 x 2048]
    tc_gemm<<<dim3(32, 32, 1), 256, SM_TOTAL>>>(
        hidp, wqp, qp, HID, P_HID, P_HID, P_HID,
        1, 0, 0, 0, 0, 0, 0, 1.0f, 0, 0, 1);

    cvt_pack_kernel<<<256,  256>>>(Wv, wvp, (long)HD * HID / 4, HID);          // 4
    cvt_pack_kernel<<<1024, 256>>>(Wo, wop, (long)HID * HID / 4, HID);         // 5

    // K = hidden @ Wk^T -> packed k [4096 x 256]
    tc_gemm<<<dim3(4, 32, 1), 256, SM_TOTAL>>>(
        hidp, wkp, kp, HID, P_HID, P_HID, P_HD,
        1, 0, 0, 0, 0, 0, 0, 1.0f, 0, 0, 1);

    // V^T[b] = Wv @ hidden[b]^T -> packed vt [2 x 256 x 2048]
    tc_gemm<<<dim3(32, 2, Bsz), 256, SM_TOTAL>>>(
        wvp, hidp, vtp, HID, P_HID, P_HID, P_SEQ,
        1, 0, 0, (long)SEQ * P_HID, 0, (long)HD * P_SEQ, 0, 1.0f, 0, 0, 1);

    // RoPE
    rope_table_kernel<<<128, 256>>>();
    rope_apply_kernel<<<MROWS * NH, 128>>>(qp, NH, P_HID);
    rope_apply_kernel<<<MROWS, 128>>>(kp, 1, P_HD);

    // scores[z=b*H+h] = q_bh @ k_b^T * scale  (fp32 out, causal block skip)
    tc_gemm<<<dim3(32, 16, Bsz * NH), 256, SM_TOTAL>>>(
        qp, kp, (char*)sc, HD,
        P_HID, P_HD, P_SEQ,
        NH,
        (long)SEQ * P_HID, 1024,
        (long)SEQ * P_HD, 0,
        (long)NH * SEQ * P_SEQ, (long)SEQ * P_SEQ,
        SCALE, 1, 0, 0);

    softmax_kernel<<<Bsz * NH * SEQ, 256>>>(sc);

    // attn[z] = probs @ V  (packed probs hi, kcausal; packed hi-only out)
    tc_gemm<<<dim3(4, 16, Bsz * NH), 256, SM_TOTAL>>>(
        (char*)sc, vtp, attnp, SEQ,
        P_SEQ, P_SEQ, P_HID,
        NH,
        (long)NH * SEQ * P_SEQ, (long)SEQ * P_SEQ,
        (long)HD * P_SEQ, 0,
        (long)SEQ * P_HID, 1024,
        1.0f, 0, 1, 2);

    // out = attn @ Wo^T : fp32 [4096 x 2048]
    tc_gemm<<<dim3(32, 32, 1), 256, SM_TOTAL>>>(
        attnp, wop, out, HID, P_HID, P_HID, P_HID,
        1, 0, 0, 0, 0, 0, 0, 1.0f, 0, 0, 0);
}

// round 16
// speedup vs baseline: 1.7994x; 1.7994x over previous
#include <cuda_runtime.h>
#include <cuda_fp16.h>
#include <math.h>
#include <stdint.h>

#define Bsz 2
#define SEQ 2048
#define HID 2048
#define NH 8
#define HD 256
#define MROWS (Bsz*SEQ)          // 4096
#define SCALE 0.0625f

// ---------------- scratch (plain fp16 row-major unless noted) ----------------
__device__ __align__(128) __half g_hidp[(size_t)MROWS * HID];
__device__ __align__(128) __half g_wqp [(size_t)HID * HID];
__device__ __align__(128) __half g_wkp [(size_t)HD * HID];
__device__ __align__(128) __half g_wvp [(size_t)HD * HID];
__device__ __align__(128) __half g_wop [(size_t)HID * HID];
__device__ __align__(128) __half g_qp  [(size_t)MROWS * NH * HD];
__device__ __align__(128) __half g_kp  [(size_t)MROWS * HD];
__device__ __align__(128) __half g_vtp [(size_t)Bsz * HD * SEQ];
__device__ __align__(128) __half g_attnp[(size_t)MROWS * NH * HD];
__device__ __align__(128) float g_scores[(size_t)Bsz * NH * SEQ * SEQ]; // fp32 scores, fp16 probs in place
__device__ float g_cos[SEQ * 128];
__device__ float g_sin[SEQ * 128];

// ---------------- helpers ----------------
#define SWZ(x) ((x) ^ (((x) >> 3) & 0x70))

__device__ __forceinline__ uint32_t smem_u32(const void* p) {
    uint32_t a;
    asm("{ .reg .u64 t; cvta.to.shared.u64 t, %1; cvt.u32.u64 %0, t; }"
        : "=r"(a) : "l"(p));
    return a;
}

#define CP16(dst, src) \
    asm volatile("cp.async.ca.shared.global [%0], [%1], 16;" \
                 :: "r"(dst), "l"(src) : "memory")
#define CP_COMMIT() asm volatile("cp.async.commit_group;" ::: "memory")
#define CP_WAIT1()  asm volatile("cp.async.wait_group 1;" ::: "memory")
#define CP_WAIT0()  asm volatile("cp.async.wait_group 0;" ::: "memory")

#define LDM4(r, a)                                                            \
    asm volatile("ldmatrix.sync.aligned.m8n8.x4.shared.b16 {%0,%1,%2,%3}, [%4];" \
        : "=r"((r)[0]), "=r"((r)[1]), "=r"((r)[2]), "=r"((r)[3]) : "r"(a))

#define MMA_F32(d, a, b0, b1)                                                 \
    asm volatile("mma.sync.aligned.m16n8k16.row.col.f32.f16.f16.f32 "         \
        "{%0,%1,%2,%3},{%4,%5,%6,%7},{%8,%9},{%0,%1,%2,%3};"                  \
        : "+f"((d)[0]), "+f"((d)[1]), "+f"((d)[2]), "+f"((d)[3])              \
        : "r"((a)[0]), "r"((a)[1]), "r"((a)[2]), "r"((a)[3]),                 \
          "r"(b0), "r"(b1))

// ---------------- pre-convert fp32 -> fp16 ----------------
__global__ __launch_bounds__(256)
void cvt_pack_kernel(const float* __restrict__ src, __half* __restrict__ dst,
                     long n_e4)
{
    long stride = (long)gridDim.x * blockDim.x;
    for (long e4 = (long)blockIdx.x * blockDim.x + threadIdx.x; e4 < n_e4; e4 += stride) {
        long e = e4 * 4;
        float4 v = *(const float4*)(src + e);
        __half2 a = __halves2half2(__float2half_rn(v.x), __float2half_rn(v.y));
        __half2 b = __halves2half2(__float2half_rn(v.z), __float2half_rn(v.w));
        *(uint2*)(dst + e) = make_uint2(*(uint32_t*)&a, *(uint32_t*)&b);
    }
}

// ---------------- HMMA GEMM, plain fp16 operands ----------------
// C[m,n] = alpha * sum_k A[m,k]*B[n,k]; A,B fp16 k-contiguous (pitch bytes pa/pb).
// CTA 128m x 128n, 8 warps (4m x 2n), warp tile 32x64, BK=64, 3 stages, 2 CTAs/SM.
// Stage 32KB: A 128x128B + B 128x128B (SW128 swizzled).
#define STG(s) ((s) * 32768)
#define SM_TOTAL 98304

__global__ __launch_bounds__(256, 2)
void tc_gemm(const char* __restrict__ A, const char* __restrict__ B,
             char* __restrict__ C, int K,
             long pa, long pb, long pc,
             int zdiv, long za_div, long za_mod, long zb_div, long zb_mod,
             long zc_div, long zc_mod, float alpha,
             int causal, int kcausal, int pack_out)
{
    extern __shared__ char smem[];
    int z = blockIdx.z;
    A += (long)(z / zdiv) * za_div + (long)(z % zdiv) * za_mod;
    B += (long)(z / zdiv) * zb_div + (long)(z % zdiv) * zb_mod;
    C += (long)(z / zdiv) * zc_div + (long)(z % zdiv) * zc_mod;
    int bm = blockIdx.y * 128;
    int bn = blockIdx.x * 128;
    if (causal && bn > bm + 127) return;
    if (kcausal && K > bm + 128) K = bm + 128;

    uint32_t sb = smem_u32(smem);
    int tid = threadIdx.x, lane = tid & 31, wid = tid >> 5;
    int wm = wid >> 1;          // 0..3 (32-row slab)
    int wn = wid & 1;           // 0..1 (64-col slab)

// iter i2 covers k = i2*64 .. i2*64+63 (128B per row)
#define ISSUE_STAGE(st, i2) do {                                              \
    _Pragma("unroll")                                                         \
    for (int j = 0; j < 4; j++) {                                             \
        int idx = tid + j * 256;                                              \
        int r = idx >> 3, c = idx & 7;                                        \
        uint32_t sw = SWZ(r * 128 + c * 16);                                  \
        CP16(sb + STG(st) + sw,                                               \
             A + (long)(bm + r) * pa + (long)(i2) * 128 + c * 16);            \
    }                                                                         \
    _Pragma("unroll")                                                         \
    for (int j = 0; j < 4; j++) {                                             \
        int idx = tid + j * 256;                                              \
        int r = idx >> 3, c = idx & 7;                                        \
        uint32_t sw = SWZ(r * 128 + c * 16);                                  \
        CP16(sb + STG(st) + 16384 + sw,                                       \
             B + (long)(bn + r) * pb + (long)(i2) * 128 + c * 16);            \
    }                                                                         \
    CP_COMMIT();                                                              \
} while (0)

    float acc[2][8][4] = {};
    const int niter = K / 64;

    ISSUE_STAGE(0, 0);
    if (niter > 1) ISSUE_STAGE(1, 1);

    const int a_off0 = (wm * 32 + (lane & 15)) * 128 + (lane >> 4) * 16;
    const int b_off0 = (wn * 64 + (lane & 7) + ((lane >> 4) & 1) * 8) * 128
                     + ((lane >> 3) & 1) * 16;

    for (int i = 0; i < niter; i++) {
        int remaining = niter - 1 - i;
        if (remaining >= 1) CP_WAIT1(); else CP_WAIT0();
        __syncthreads();   // stage i%3 ready; all warps done MMA(i-1)

        if (i + 2 < niter) ISSUE_STAGE((i + 2) % 3, i + 2);

        uint32_t aB = sb + STG(i % 3);
        uint32_t bB = aB + 16384;
        #pragma unroll
        for (int ks = 0; ks < 4; ks++) {     // 4 x k16 chunks within 64 k's
            uint32_t ah[2][4];
            #pragma unroll
            for (int mt = 0; mt < 2; mt++) {
                int off = a_off0 + mt * 16 * 128 + ks * 32;
                LDM4(ah[mt], aB + SWZ(off));
            }
            #pragma unroll
            for (int np = 0; np < 4; np++) {
                uint32_t bh[4];
                int off = b_off0 + np * 16 * 128 + ks * 32;
                LDM4(bh, bB + SWZ(off));
                #pragma unroll
                for (int mt = 0; mt < 2; mt++) {
                    #pragma unroll
                    for (int t = 0; t < 2; t++) {
                        MMA_F32(acc[mt][np * 2 + t], ah[mt], bh[t * 2], bh[t * 2 + 1]);
                    }
                }
            }
        }
    }

    // epilogue: pack_out 1 = fp16, 0 = fp32
    int r0 = bm + wm * 32 + (lane >> 2);
    int c0 = bn + wn * 64 + (lane & 3) * 2;
    #pragma unroll
    for (int mt = 0; mt < 2; mt++) {
        #pragma unroll
        for (int nt = 0; nt < 8; nt++) {
            float* d = acc[mt][nt];
            int c = c0 + nt * 8;
            #pragma unroll
            for (int half = 0; half < 2; half++) {
                long row = r0 + mt * 16 + half * 8;
                float v0 = d[half * 2 + 0] * alpha;
                float v1 = d[half * 2 + 1] * alpha;
                if (pack_out) {
                    __half2 hp = __halves2half2(__float2half_rn(v0), __float2half_rn(v1));
                    *(uint32_t*)(C + row * pc + (long)c * 2) = *(uint32_t*)&hp;
                } else {
                    *(float2*)(C + row * pc + (long)c * 4) = make_float2(v0, v1);
                }
            }
        }
    }
}

// ---------------- RoPE ----------------
__global__ void rope_table_kernel()
{
    int d = blockIdx.x;
    double inv = exp(-((double)d / 128.0) * 9.210340371976184);
    const double INV2PI = 0.15915494309189535;
    const double PI2_HI = 6.283185307179586;
    const double PI2_LO = 2.4492935982947064e-16;
    for (int s = threadIdx.x; s < SEQ; s += blockDim.x) {
        double ang = (double)s * inv;
        double n = rint(ang * INV2PI);
        double r = fma(-n, PI2_HI, ang);
        r = fma(-n, PI2_LO, r);
        float rf = (float)r;
        g_cos[s * 128 + d] = cosf(rf);
        g_sin[s * 128 + d] = sinf(rf);
    }
}

__global__ void rope_apply_kernel(__half* __restrict__ x, int heads, long pitch_elts)
{
    long blk = blockIdx.x;
    long rowIdx = blk / heads;
    int h = (int)(blk % heads);
    int s = (int)(rowIdx % SEQ);
    int d = threadIdx.x;
    __half* base = x + rowIdx * pitch_elts + (long)h * 256;

    float x1 = __half2float(base[d]);
    float x2 = __half2float(base[d + 128]);
    float c  = g_cos[s * 128 + d];
    float si = g_sin[s * 128 + d];
    base[d]       = __float2half_rn(x1 * c - x2 * si);
    base[d + 128] = __float2half_rn(x2 * c + x1 * si);
}

// ---------------- causal softmax: fp32 in, fp16 out in place --------------
__global__ __launch_bounds__(256)
void softmax_kernel(float* __restrict__ scores)
{
    long row = blockIdx.x;
    int s = (int)(row % SEQ);
    int valid = s + 1;
    float* p = scores + row * (long)SEQ;
    int tid = threadIdx.x;

    float vals[8];
    float mx = -INFINITY;
    #pragma unroll
    for (int i = 0; i < 8; i++) {
        int c = tid + i * 256;
        vals[i] = (c < valid) ? p[c] : -INFINITY;
        mx = fmaxf(mx, vals[i]);
    }
    __shared__ float red[8];
    #pragma unroll
    for (int o = 16; o > 0; o >>= 1) mx = fmaxf(mx, __shfl_xor_sync(0xffffffffu, mx, o));
    if ((tid & 31) == 0) red[tid >> 5] = mx;
    __syncthreads();
    if (tid < 32) {
        float m = (tid < 8) ? red[tid] : -INFINITY;
        #pragma unroll
        for (int o = 4; o > 0; o >>= 1) m = fmaxf(m, __shfl_xor_sync(0xffffffffu, m, o));
        if (tid == 0) red[0] = m;
    }
    __syncthreads();
    mx = red[0];

    float sum = 0.f;
    #pragma unroll
    for (int i = 0; i < 8; i++) {
        int c = tid + i * 256;
        float e = (c < valid) ? __expf(vals[i] - mx) : 0.f;
        vals[i] = e;
        sum += e;
    }
    __shared__ float red2[8];
    #pragma unroll
    for (int o = 16; o > 0; o >>= 1) sum += __shfl_xor_sync(0xffffffffu, sum, o);
    if ((tid & 31) == 0) red2[tid >> 5] = sum;
    __syncthreads();
    if (tid < 32) {
        float m = (tid < 8) ? red2[tid] : 0.f;
        #pragma unroll
        for (int o = 4; o > 0; o >>= 1) m += __shfl_xor_sync(0xffffffffu, m, o);
        if (tid == 0) red2[0] = m;
    }
    __syncthreads();
    float inv = 1.0f / red2[0];

    __half* ph = (__half*)p;
    #pragma unroll
    for (int i = 0; i < 8; i++) {
        int c = tid + i * 256;
        ph[c] = __float2half_rn(vals[i] * inv);
    }
}

// ---------------- launch ----------------
extern "C" void kernel_launch(void* const* d_in, const int* in_sizes, int n_in,
                              void* d_out, int out_size)
{
    const float* hidden = (const float*)d_in[0];
    const float* Wq = (const float*)d_in[3];
    const float* Wk = (const float*)d_in[4];
    const float* Wv = (const float*)d_in[5];
    const float* Wo = (const float*)d_in[6];
    char* out = (char*)d_out;

    __half *hidp, *wqp, *wkp, *wvp, *wop, *qp, *kp, *vtp, *attnp;
    float* sc;
    cudaGetSymbolAddress((void**)&hidp,  g_hidp);
    cudaGetSymbolAddress((void**)&wqp,   g_wqp);
    cudaGetSymbolAddress((void**)&wkp,   g_wkp);
    cudaGetSymbolAddress((void**)&wvp,   g_wvp);
    cudaGetSymbolAddress((void**)&wop,   g_wop);
    cudaGetSymbolAddress((void**)&qp,    g_qp);
    cudaGetSymbolAddress((void**)&kp,    g_kp);
    cudaGetSymbolAddress((void**)&vtp,   g_vtp);
    cudaGetSymbolAddress((void**)&attnp, g_attnp);
    cudaGetSymbolAddress((void**)&sc,    g_scores);

    cudaFuncSetAttribute(tc_gemm, cudaFuncAttributeMaxDynamicSharedMemorySize, SM_TOTAL);

    const long P_HID = (long)HID * 2;       // 4096B fp16 pitch
    const long P_HD  = (long)HD * 2;        // 512B
    const long P_SEQ16 = (long)SEQ * 2;     // 4096B (vtp)
    const long P_SC   = (long)SEQ * 4;      // 8192B (scores buffer row pitch)

    // launches ordered so Q GEMM is index 3 (ncu profiles launch idx 3)
    cvt_pack_kernel<<<2048, 256>>>(hidden, hidp, (long)MROWS * HID / 4);  // 0
    cvt_pack_kernel<<<1024, 256>>>(Wq, wqp, (long)HID * HID / 4);         // 1
    cvt_pack_kernel<<<256,  256>>>(Wk, wkp, (long)HD * HID / 4);          // 2

    // 3: Q = hidden @ Wq^T -> fp16 q [4096 x 2048]
    tc_gemm<<<dim3(16, 32, 1), 256, SM_TOTAL>>>(
        (char*)hidp, (char*)wqp, (char*)qp, HID, P_HID, P_HID, P_HID,
        1, 0, 0, 0, 0, 0, 0, 1.0f, 0, 0, 1);

    cvt_pack_kernel<<<256,  256>>>(Wv, wvp, (long)HD * HID / 4);          // 4
    cvt_pack_kernel<<<1024, 256>>>(Wo, wop, (long)HID * HID / 4);         // 5

    // K = hidden @ Wk^T -> fp16 k [4096 x 256]
    tc_gemm<<<dim3(2, 32, 1), 256, SM_TOTAL>>>(
        (char*)hidp, (char*)wkp, (char*)kp, HID, P_HID, P_HID, P_HD,
        1, 0, 0, 0, 0, 0, 0, 1.0f, 0, 0, 1);

    // V^T[b] = Wv @ hidden[b]^T -> fp16 vt [2 x 256 x 2048]
    tc_gemm<<<dim3(16, 2, Bsz), 256, SM_TOTAL>>>(
        (char*)wvp, (char*)hidp, (char*)vtp, HID, P_HID, P_HID, P_SEQ16,
        1, 0, 0, (long)SEQ * P_HID, 0, (long)HD * P_SEQ16, 0, 1.0f, 0, 0, 1);

    // RoPE
    rope_table_kernel<<<128, 256>>>();
    rope_apply_kernel<<<MROWS * NH, 128>>>(qp, NH, HID);
    rope_apply_kernel<<<MROWS, 128>>>(kp, 1, HD);

    // scores[z=b*H+h] = q_bh @ k_b^T * scale  (fp32 out, causal block skip)
    tc_gemm<<<dim3(16, 16, Bsz * NH), 256, SM_TOTAL>>>(
        (char*)qp, (char*)kp, (char*)sc, HD,
        P_HID, P_HD, P_SC,
        NH,
        (long)SEQ * P_HID, 512,             // A: batch rows, head offset 256 elts
        (long)SEQ * P_HD, 0,                // B: batch
        (long)NH * SEQ * P_SC, (long)SEQ * P_SC,
        SCALE, 1, 0, 0);

    softmax_kernel<<<Bsz * NH * SEQ, 256>>>(sc);

    // attn[z] = probs @ V  (probs fp16 rows with fp32-row pitch, kcausal)
    tc_gemm<<<dim3(2, 16, Bsz * NH), 256, SM_TOTAL>>>(
        (char*)sc, (char*)vtp, (char*)attnp, SEQ,
        P_SC, P_SEQ16, P_HID,
        NH,
        (long)NH * SEQ * P_SC, (long)SEQ * P_SC,
        (long)HD * P_SEQ16, 0,
        (long)SEQ * P_HID, 512,
        1.0f, 0, 1, 1);

    // out = attn @ Wo^T : fp32 [4096 x 2048]
    tc_gemm<<<dim3(16, 32, 1), 256, SM_TOTAL>>>(
        (char*)attnp, (char*)wop, out, HID, P_HID, P_HID, P_SC,
        1, 0, 0, 0, 0, 0, 0, 1.0f, 0, 0, 0);
}